// round 5
// baseline (speedup 1.0000x reference)
#include <cuda_runtime.h>
#include <cuda_bf16.h>

// Problem: M=8192 matches, WW=64 (8x8), C=96; whole feats (2,96,320,320);
// coarse 80x80, scale_f_c=4, final scale=2. dim2=192.

#define M_MATCH 8192

static const size_t CONF_OFF  = 0ull;
static const size_t MCONF_OFF = 33554432ull;   // 8192*4096
static const size_t MK0_OFF   = 33562624ull;   // +8192
static const size_t MK1_OFF   = 33579008ull;   // +16384
static const size_t VALID_OFF = 33595392ull;   // +16384

// ------------------------- static device scratch ---------------------------
__device__ int4          g_coords[M_MATCH];                 // x0,y0,x1,y1 (fine, unscaled)
__device__ __nv_bfloat16 g_A1[1728 * 1728];                 // conv1 effective matrix [n=oc*9+p][k=q*192+ic]
__device__ __nv_bfloat16 g_W2b[192 * 1728];                 // [oc2][oc1*9+p]
__device__ __nv_bfloat16 g_X[(size_t)M_MATCH * 1728];       // gathered patches [m][q*192+ic]
__device__ __nv_bfloat16 g_R[(size_t)M_MATCH * 1728];       // lrelu(conv1) [m][oc1*9+p]
__device__ float         g_out2[(size_t)M_MATCH * 192];     // lrelu(conv2) [m][oc2]

__device__ __forceinline__ float lrelu(float x) { return x > 0.f ? x : 0.01f * x; }

__device__ __forceinline__ void mma16816(float* c, unsigned a0, unsigned a1,
                                         unsigned a2, unsigned a3,
                                         unsigned b0, unsigned b1) {
    asm volatile(
        "mma.sync.aligned.m16n8k16.row.col.f32.bf16.bf16.f32 "
        "{%0,%1,%2,%3}, {%4,%5,%6,%7}, {%8,%9}, {%0,%1,%2,%3};"
        : "+f"(c[0]), "+f"(c[1]), "+f"(c[2]), "+f"(c[3])
        : "r"(a0), "r"(a1), "r"(a2), "r"(a3), "r"(b0), "r"(b1));
}

__device__ __forceinline__ void cpasync16(void* s, const void* g) {
    unsigned sa = (unsigned)__cvta_generic_to_shared(s);
    asm volatile("cp.async.cg.shared.global [%0], [%1], 16;\n" :: "r"(sa), "l"(g));
}

// ---------------------------------------------------------------------------
// K0: build bf16 weight matrices
//   g_A1[(oc*9+p)*1728 + q*192+ic] = w1[oc][ic][ky][kx] with ky=q/3-p/3+1, kx=q%3-p%3+1 (0 if tap invalid)
//   g_W2b = cast(w2)   (w2 layout (oc2, ic2, 3,3) == [oc2][ic2*9+p])
// ---------------------------------------------------------------------------
__global__ void k0_w(const float* __restrict__ w1, const float* __restrict__ w2) {
    int idx = blockIdx.x * 256 + threadIdx.x;
    const int NA1 = 1728 * 1728;
    if (idx < NA1) {
        int n = idx / 1728, k = idx - n * 1728;
        int oc = n / 9, p = n - oc * 9;
        int q = k / 192, ic = k - q * 192;
        int ky = q / 3 - p / 3 + 1;
        int kx = q % 3 - p % 3 + 1;
        float v = 0.f;
        if ((unsigned)ky < 3u && (unsigned)kx < 3u)
            v = w1[(oc * 192 + ic) * 9 + ky * 3 + kx];
        g_A1[idx] = __float2bfloat16(v);
    } else {
        int j = idx - NA1;
        if (j < 192 * 1728) g_W2b[j] = __float2bfloat16(w2[j]);
    }
}

// ---------------------------------------------------------------------------
// K1: per-match sim (fp32), dual softmax, conf write, argmax -> g_coords
// one block per match, 128 threads, 70912 B dynamic smem
// ---------------------------------------------------------------------------
__global__ void k1_sim(const float* __restrict__ f0u, const float* __restrict__ f1u,
                       const int* __restrict__ i_ids_c, const int* __restrict__ j_ids_c,
                       float* __restrict__ out) {
    extern __shared__ float sm[];
    float* f0T  = sm;                  // [96][68]
    float* f1T  = sm + 6528;           // [96][68]
    float* S    = sm + 13056;          // [64][65]
    float* rm   = S + 4160;            // 64
    float* rinv = rm + 64;
    float* cm   = rinv + 64;
    float* cinv = cm + 64;
    float* redv = cinv + 64;           // 128
    int*   redi = (int*)(redv + 128);  // 128

    const int m   = blockIdx.x;
    const int tid = threadIdx.x;
    const float* f0 = f0u + (size_t)m * 6144;
    const float* f1 = f1u + (size_t)m * 6144;

    for (int i = tid; i < 6144; i += 128) {
        int l = i / 96;
        int c = i - l * 96;
        f0T[c * 68 + l] = f0[i];
        f1T[c * 68 + l] = f1[i];
    }
    __syncthreads();

    const int tl = tid & 15, ts = tid >> 4;   // 16 x 8 thread grid, 4x8 regs each
    const float4* aT = (const float4*)f0T;
    const float4* bT = (const float4*)f1T;
    float acc[4][8];
#pragma unroll
    for (int i = 0; i < 4; ++i)
#pragma unroll
        for (int j = 0; j < 8; ++j) acc[i][j] = 0.f;

#pragma unroll 8
    for (int c = 0; c < 96; ++c) {
        float4 a4  = aT[c * 17 + tl];
        float4 b04 = bT[c * 17 + 2 * ts];
        float4 b14 = bT[c * 17 + 2 * ts + 1];
        float av[4] = {a4.x, a4.y, a4.z, a4.w};
        float bv[8] = {b04.x, b04.y, b04.z, b04.w, b14.x, b14.y, b14.z, b14.w};
#pragma unroll
        for (int i = 0; i < 4; ++i)
#pragma unroll
            for (int j = 0; j < 8; ++j) acc[i][j] = fmaf(av[i], bv[j], acc[i][j]);
    }

    const float ALPHA = 1.0f / 9.6f;   // (1/C) / TEMP
    const int l0 = tl * 4, s0 = ts * 8;
#pragma unroll
    for (int i = 0; i < 4; ++i)
#pragma unroll
        for (int j = 0; j < 8; ++j) S[(l0 + i) * 65 + s0 + j] = acc[i][j] * ALPHA;
    __syncthreads();

    if (tid < 64) {                    // softmax over s (axis=2), per row l
        int l = tid;
        float mx = -1e30f;
        for (int s = 0; s < 64; ++s) mx = fmaxf(mx, S[l * 65 + s]);
        float sum = 0.f;
        for (int s = 0; s < 64; ++s) sum += __expf(S[l * 65 + s] - mx);
        rm[l] = mx; rinv[l] = 1.f / sum;
    } else {                           // softmax over l (axis=1), per col s
        int s = tid - 64;
        float mx = -1e30f;
        for (int l = 0; l < 64; ++l) mx = fmaxf(mx, S[l * 65 + s]);
        float sum = 0.f;
        for (int l = 0; l < 64; ++l) sum += __expf(S[l * 65 + s] - mx);
        cm[s] = mx; cinv[s] = 1.f / sum;
    }
    __syncthreads();

    float best = -1.f; int bidx = 0;
    float* outc = out + (size_t)m * 4096;
    for (int i = tid; i < 4096; i += 128) {
        int l = i >> 6, s = i & 63;
        float v = __expf(2.f * S[l * 65 + s] - rm[l] - cm[s]) * rinv[l] * cinv[s];
        outc[i] = v;
        if (v > best) { best = v; bidx = i; }
    }
    redv[tid] = best; redi[tid] = bidx;
    __syncthreads();

    if (tid == 0) {
        float b = redv[0]; int bi = redi[0];
        for (int t = 1; t < 128; ++t) {
            float v = redv[t];
            if (v > b || (v == b && redi[t] < bi)) { b = v; bi = redi[t]; }
        }
        bool valid = b > 0.01f;
        out[MCONF_OFF + m] = valid ? b : 0.f;
        out[VALID_OFF + m] = valid ? 1.f : 0.f;
        int l = bi >> 6, s = bi & 63;
        int ii = i_ids_c[m], jj = j_ids_c[m];
        int x0 = (ii % 80) * 4 + (l & 7) - 4;
        int y0 = (ii / 80) * 4 + (l >> 3) - 4;
        int x1 = (jj % 80) * 4 + (s & 7) - 4;
        int y1 = (jj / 80) * 4 + (s >> 3) - 4;
        g_coords[m] = make_int4(x0, y0, x1, y1);
    }
}

// ---------------------------------------------------------------------------
// K2: gather 3x3 patches (zero pad) -> g_X[m][q*192 + icc] (coalesced writes)
// 2 matches per block, 192 threads (thread = (match_local, ic))
// ---------------------------------------------------------------------------
__global__ void k2_gather(const float* __restrict__ f0w, const float* __restrict__ f1w,
                          const int* __restrict__ b_ids) {
    const int t  = threadIdx.x;
    const int ml = t / 96, ic = t - ml * 96;
    const int m  = blockIdx.x * 2 + ml;
    const int4 cd = g_coords[m];
    const int b = b_ids[m];
    const float* b0 = f0w + ((size_t)b * 96 + ic) * 102400;
    const float* b1 = f1w + ((size_t)b * 96 + ic) * 102400;
    __nv_bfloat16* X = g_X + (size_t)m * 1728;
#pragma unroll
    for (int q = 0; q < 9; ++q) {
        int dy = q / 3, dx = q - dy * 3;
        int y = cd.y - 1 + dy, x = cd.x - 1 + dx;
        float v0 = ((unsigned)y < 320u && (unsigned)x < 320u) ? b0[y * 320 + x] : 0.f;
        X[q * 192 + ic] = __float2bfloat16(v0);
        y = cd.w - 1 + dy; x = cd.z - 1 + dx;
        float v1 = ((unsigned)y < 320u && (unsigned)x < 320u) ? b1[y * 320 + x] : 0.f;
        X[q * 192 + 96 + ic] = __float2bfloat16(v1);
    }
}

// ---------------------------------------------------------------------------
// K3: bf16 mma GEMM, 128x64x32 tiles, 256 thr (8 warps, 4m x 2n, warp=32x32)
// which==0: g_X(8192x1728) @ g_A1[n][k]  -> lrelu -> g_R bf16 (ld 1728)
// which==1: g_R(8192x1728) @ g_W2b[n][k] -> lrelu -> g_out2 f32 (ld 192)
// ---------------------------------------------------------------------------
__global__ void __launch_bounds__(256) k3_gemm(int which) {
    __shared__ __align__(16) __nv_bfloat16 As[2][128 * 40];
    __shared__ __align__(16) __nv_bfloat16 Bs[2][64 * 40];

    const __nv_bfloat16* A  = which ? g_R   : g_X;
    const __nv_bfloat16* Bm = which ? g_W2b : g_A1;
    const int ldc = which ? 192 : 1728;

    const int tid = threadIdx.x;
    const int rowbase = blockIdx.x * 128;
    const int colbase = blockIdx.y * 64;
    const int warp = tid >> 5, lane = tid & 31;
    const int wm = warp & 3, wn = warp >> 2;
    const int gid = lane >> 2, tq = lane & 3;

    float c[2][4][4];
#pragma unroll
    for (int i = 0; i < 2; ++i)
#pragma unroll
        for (int j = 0; j < 4; ++j)
#pragma unroll
            for (int r = 0; r < 4; ++r) c[i][j][r] = 0.f;

    auto copy = [&](int buf, int kt) {
        int k0 = kt * 32;
#pragma unroll
        for (int u = 0; u < 2; ++u) {
            int ch = tid + u * 256;
            int r = ch >> 2, sg = ch & 3;
            cpasync16(&As[buf][r * 40 + sg * 8],
                      A + (size_t)(rowbase + r) * 1728 + k0 + sg * 8);
        }
        {
            int r = tid >> 2, sg = tid & 3;
            cpasync16(&Bs[buf][r * 40 + sg * 8],
                      Bm + (size_t)(colbase + r) * 1728 + k0 + sg * 8);
        }
    };

    copy(0, 0);
    asm volatile("cp.async.commit_group;");
    const int KT = 54;                         // 1728/32
    for (int kt = 0; kt < KT; ++kt) {
        int buf = kt & 1;
        if (kt + 1 < KT) {
            copy(buf ^ 1, kt + 1);
            asm volatile("cp.async.commit_group;");
            asm volatile("cp.async.wait_group 1;");
        } else {
            asm volatile("cp.async.wait_group 0;");
        }
        __syncthreads();
        const __nv_bfloat16* Ab = As[buf];
        const __nv_bfloat16* Bb = Bs[buf];
#pragma unroll
        for (int kk = 0; kk < 32; kk += 16) {
            unsigned a[2][4], b[4][2];
#pragma unroll
            for (int mt = 0; mt < 2; ++mt) {
                int r0 = wm * 32 + mt * 16 + gid;
                const unsigned* p0 = (const unsigned*)(Ab + r0 * 40 + kk + tq * 2);
                const unsigned* p1 = (const unsigned*)(Ab + (r0 + 8) * 40 + kk + tq * 2);
                a[mt][0] = p0[0]; a[mt][1] = p1[0];
                a[mt][2] = p0[4]; a[mt][3] = p1[4];
            }
#pragma unroll
            for (int nt = 0; nt < 4; ++nt) {
                const unsigned* q0 =
                    (const unsigned*)(Bb + (wn * 32 + nt * 8 + gid) * 40 + kk + tq * 2);
                b[nt][0] = q0[0]; b[nt][1] = q0[4];
            }
#pragma unroll
            for (int mt = 0; mt < 2; ++mt)
#pragma unroll
                for (int nt = 0; nt < 4; ++nt)
                    mma16816(c[mt][nt], a[mt][0], a[mt][1], a[mt][2], a[mt][3],
                             b[nt][0], b[nt][1]);
        }
        __syncthreads();
    }

#pragma unroll
    for (int mt = 0; mt < 2; ++mt)
#pragma unroll
        for (int nt = 0; nt < 4; ++nt) {
            int r0 = rowbase + wm * 32 + mt * 16 + gid;
            int c0 = colbase + wn * 32 + nt * 8 + tq * 2;
            float v00 = lrelu(c[mt][nt][0]), v01 = lrelu(c[mt][nt][1]);
            float v10 = lrelu(c[mt][nt][2]), v11 = lrelu(c[mt][nt][3]);
            if (!which) {
                *(__nv_bfloat162*)(g_R + (size_t)r0 * 1728 + c0) =
                    __floats2bfloat162_rn(v00, v01);
                *(__nv_bfloat162*)(g_R + (size_t)(r0 + 8) * 1728 + c0) =
                    __floats2bfloat162_rn(v10, v11);
            } else {
                *(float2*)(g_out2 + (size_t)r0 * 192 + c0) = make_float2(v00, v01);
                *(float2*)(g_out2 + (size_t)(r0 + 8) * 192 + c0) = make_float2(v10, v11);
            }
        }
}

// ---------------------------------------------------------------------------
// K4: conv3 (1x1, 4 outs) + tanh + mkpts. One warp per match.
// ---------------------------------------------------------------------------
__global__ void k4_fin(const float* __restrict__ w3, float* __restrict__ out) {
    const int m = blockIdx.x * 8 + (threadIdx.x >> 5);
    const int lane = threadIdx.x & 31;
    const float* r = g_out2 + (size_t)m * 192;
    float a0 = 0.f, a1 = 0.f, a2 = 0.f, a3 = 0.f;
#pragma unroll
    for (int i = lane; i < 192; i += 32) {
        float v = r[i];
        a0 += w3[i] * v;
        a1 += w3[192 + i] * v;
        a2 += w3[384 + i] * v;
        a3 += w3[576 + i] * v;
    }
#pragma unroll
    for (int o = 16; o; o >>= 1) {
        a0 += __shfl_xor_sync(0xffffffffu, a0, o);
        a1 += __shfl_xor_sync(0xffffffffu, a1, o);
        a2 += __shfl_xor_sync(0xffffffffu, a2, o);
        a3 += __shfl_xor_sync(0xffffffffu, a3, o);
    }
    if (lane == 0) {
        int4 cd = g_coords[m];
        out[MK0_OFF + 2 * m]     = ((float)cd.x + tanhf(a0) * 0.5f) * 2.f;
        out[MK0_OFF + 2 * m + 1] = ((float)cd.y + tanhf(a1) * 0.5f) * 2.f;
        out[MK1_OFF + 2 * m]     = ((float)cd.z + tanhf(a2) * 0.5f) * 2.f;
        out[MK1_OFF + 2 * m + 1] = ((float)cd.w + tanhf(a3) * 0.5f) * 2.f;
    }
}

// ---------------------------------------------------------------------------
extern "C" void kernel_launch(void* const* d_in, const int* in_sizes, int n_in,
                              void* d_out, int out_size) {
    const float* f0u  = (const float*)d_in[0];
    const float* f1u  = (const float*)d_in[1];
    const float* f0w  = (const float*)d_in[2];
    const float* f1w  = (const float*)d_in[3];
    const int*   bids = (const int*)d_in[4];
    const int*   iids = (const int*)d_in[5];
    const int*   jids = (const int*)d_in[6];
    const float* w1   = (const float*)d_in[7];
    const float* w2   = (const float*)d_in[8];
    const float* w3   = (const float*)d_in[9];
    float* out = (float*)d_out;

    cudaFuncSetAttribute(k1_sim, cudaFuncAttributeMaxDynamicSharedMemorySize, 70912);

    k0_w<<<(1728 * 1728 + 192 * 1728 + 255) / 256, 256>>>(w1, w2);
    k1_sim<<<M_MATCH, 128, 70912>>>(f0u, f1u, iids, jids, out);
    k2_gather<<<M_MATCH / 2, 192>>>(f0w, f1w, bids);
    k3_gemm<<<dim3(64, 27), 256>>>(0);   // conv1: N=1728
    k3_gemm<<<dim3(64, 3), 256>>>(1);    // conv2: N=192
    k4_fin<<<M_MATCH / 8, 256>>>(w3, out);
}

// round 6
// speedup vs baseline: 1.1829x; 1.1829x over previous
#include <cuda_runtime.h>
#include <cuda_bf16.h>

// Problem: M=8192 matches, WW=64 (8x8), C=96; whole feats (2,96,320,320);
// coarse 80x80, scale_f_c=4, final scale=2. dim2=192.

#define M_MATCH 8192

static const size_t CONF_OFF  = 0ull;
static const size_t MCONF_OFF = 33554432ull;   // 8192*4096
static const size_t MK0_OFF   = 33562624ull;   // +8192
static const size_t MK1_OFF   = 33579008ull;   // +16384
static const size_t VALID_OFF = 33595392ull;   // +16384

// ------------------------- static device scratch ---------------------------
__device__ int4          g_coords[M_MATCH];                 // x0,y0,x1,y1 (fine, unscaled)
__device__ __nv_bfloat16 g_A1[1728 * 1728];                 // conv1 effective matrix [n=oc*9+p][k=q*192+ic]
__device__ __nv_bfloat16 g_W2b[192 * 1728];                 // [oc2][oc1*9+p]
__device__ __nv_bfloat16 g_X[(size_t)M_MATCH * 1728];       // gathered patches [m][q*192+ic]
__device__ __nv_bfloat16 g_R[(size_t)M_MATCH * 1728];       // lrelu(conv1) [m][oc1*9+p]
__device__ float         g_out2[(size_t)M_MATCH * 192];     // lrelu(conv2) [m][oc2]

__device__ __forceinline__ float lrelu(float x) { return x > 0.f ? x : 0.01f * x; }

__device__ __forceinline__ void mma16816(float* c, const unsigned* a,
                                         unsigned b0, unsigned b1) {
    asm volatile(
        "mma.sync.aligned.m16n8k16.row.col.f32.bf16.bf16.f32 "
        "{%0,%1,%2,%3}, {%4,%5,%6,%7}, {%8,%9}, {%0,%1,%2,%3};"
        : "+f"(c[0]), "+f"(c[1]), "+f"(c[2]), "+f"(c[3])
        : "r"(a[0]), "r"(a[1]), "r"(a[2]), "r"(a[3]), "r"(b0), "r"(b1));
}

__device__ __forceinline__ void ldsm4(unsigned* r, const void* p) {
    unsigned sa = (unsigned)__cvta_generic_to_shared(p);
    asm volatile("ldmatrix.sync.aligned.m8n8.x4.shared.b16 {%0,%1,%2,%3}, [%4];"
                 : "=r"(r[0]), "=r"(r[1]), "=r"(r[2]), "=r"(r[3]) : "r"(sa));
}

__device__ __forceinline__ void cpasync16(void* s, const void* g) {
    unsigned sa = (unsigned)__cvta_generic_to_shared(s);
    asm volatile("cp.async.cg.shared.global [%0], [%1], 16;\n" :: "r"(sa), "l"(g));
}

// ---------------------------------------------------------------------------
// K0: build bf16 weight matrices
// ---------------------------------------------------------------------------
__global__ void k0_w(const float* __restrict__ w1, const float* __restrict__ w2) {
    int idx = blockIdx.x * 256 + threadIdx.x;
    const int NA1 = 1728 * 1728;
    if (idx < NA1) {
        int n = idx / 1728, k = idx - n * 1728;
        int oc = n / 9, p = n - oc * 9;
        int q = k / 192, ic = k - q * 192;
        int ky = q / 3 - p / 3 + 1;
        int kx = q % 3 - p % 3 + 1;
        float v = 0.f;
        if ((unsigned)ky < 3u && (unsigned)kx < 3u)
            v = w1[(oc * 192 + ic) * 9 + ky * 3 + kx];
        g_A1[idx] = __float2bfloat16(v);
    } else {
        int j = idx - NA1;
        if (j < 192 * 1728) g_W2b[j] = __float2bfloat16(w2[j]);
    }
}

// ---------------------------------------------------------------------------
// K1: sim via bf16 2-way-split tensor MMA (hi*hi + hi*lo + lo*hi, fp32 acc),
//     dual softmax, conf write, argmax -> g_coords.
// one block per match, 128 threads (4 warps, each warp: 16 rows x 64 cols)
// dynamic smem 71936 B
// ---------------------------------------------------------------------------
__global__ void __launch_bounds__(128) k1_sim(
        const float* __restrict__ f0u, const float* __restrict__ f1u,
        const int* __restrict__ i_ids_c, const int* __restrict__ j_ids_c,
        float* __restrict__ out) {
    extern __shared__ char smraw[];
    __nv_bfloat16* f0h = (__nv_bfloat16*)smraw;   // [64][104]
    __nv_bfloat16* f0l = f0h + 6656;
    __nv_bfloat16* f1h = f0l + 6656;
    __nv_bfloat16* f1l = f1h + 6656;
    float* S    = (float*)(smraw + 53248);        // [64][65]
    float* rm   = S + 4160;                       // 64
    float* rinv = rm + 64;
    float* cm   = rinv + 64;
    float* cinv = cm + 64;
    float* redv = cinv + 64;                      // 128
    int*   redi = (int*)(redv + 128);             // 128

    const int m   = blockIdx.x;
    const int tid = threadIdx.x;
    const float* f0 = f0u + (size_t)m * 6144;
    const float* f1 = f1u + (size_t)m * 6144;

    // load fp32, split into bf16 hi/lo, store row-major [l][104]
    for (int i = tid; i < 6144; i += 128) {
        int l = i / 96, ch = i - l * 96;
        float x0 = f0[i];
        __nv_bfloat16 h0 = __float2bfloat16(x0);
        f0h[l * 104 + ch] = h0;
        f0l[l * 104 + ch] = __float2bfloat16(x0 - __bfloat162float(h0));
        float x1 = f1[i];
        __nv_bfloat16 h1 = __float2bfloat16(x1);
        f1h[l * 104 + ch] = h1;
        f1l[l * 104 + ch] = __float2bfloat16(x1 - __bfloat162float(h1));
    }
    __syncthreads();

    const int warp = tid >> 5, lane = tid & 31;
    const int mi = lane >> 3, rr = lane & 7;
    const int gid = lane >> 2, tq = lane & 3;
    // ldmatrix address components
    const int a_row = warp * 16 + (mi & 1) * 8 + rr;
    const int a_csel = (mi >> 1) * 8;
    const int b_roff = (mi >> 1) * 8 + rr;
    const int b_csel = (mi & 1) * 8;

    float c[8][4];
#pragma unroll
    for (int i = 0; i < 8; ++i)
#pragma unroll
        for (int j = 0; j < 4; ++j) c[i][j] = 0.f;

#pragma unroll
    for (int ks = 0; ks < 6; ++ks) {
        int k0 = ks * 16;
        unsigned ah[4], al[4];
        ldsm4(ah, f0h + a_row * 104 + k0 + a_csel);
        ldsm4(al, f0l + a_row * 104 + k0 + a_csel);
#pragma unroll
        for (int g = 0; g < 4; ++g) {
            int n0 = g * 16;
            unsigned bh[4], bl[4];
            ldsm4(bh, f1h + (n0 + b_roff) * 104 + k0 + b_csel);
            ldsm4(bl, f1l + (n0 + b_roff) * 104 + k0 + b_csel);
            mma16816(c[2 * g],     ah, bh[0], bh[1]);
            mma16816(c[2 * g],     ah, bl[0], bl[1]);
            mma16816(c[2 * g],     al, bh[0], bh[1]);
            mma16816(c[2 * g + 1], ah, bh[2], bh[3]);
            mma16816(c[2 * g + 1], ah, bl[2], bl[3]);
            mma16816(c[2 * g + 1], al, bh[2], bh[3]);
        }
    }

    const float ALPHA = 1.0f / 9.6f;   // (1/C)/TEMP
    {
        int r0 = warp * 16 + gid, r1 = r0 + 8;
#pragma unroll
        for (int nt = 0; nt < 8; ++nt) {
            int col = nt * 8 + tq * 2;
            S[r0 * 65 + col]     = c[nt][0] * ALPHA;
            S[r0 * 65 + col + 1] = c[nt][1] * ALPHA;
            S[r1 * 65 + col]     = c[nt][2] * ALPHA;
            S[r1 * 65 + col + 1] = c[nt][3] * ALPHA;
        }
    }
    __syncthreads();

    if (tid < 64) {                    // softmax over s (axis=2), per row l
        int l = tid;
        float mx = -1e30f;
        for (int s = 0; s < 64; ++s) mx = fmaxf(mx, S[l * 65 + s]);
        float sum = 0.f;
        for (int s = 0; s < 64; ++s) sum += __expf(S[l * 65 + s] - mx);
        rm[l] = mx; rinv[l] = 1.f / sum;
    } else {                           // softmax over l (axis=1), per col s
        int s = tid - 64;
        float mx = -1e30f;
        for (int l = 0; l < 64; ++l) mx = fmaxf(mx, S[l * 65 + s]);
        float sum = 0.f;
        for (int l = 0; l < 64; ++l) sum += __expf(S[l * 65 + s] - mx);
        cm[s] = mx; cinv[s] = 1.f / sum;
    }
    __syncthreads();

    float best = -1.f; int bidx = 0;
    float* outc = out + (size_t)m * 4096;
    for (int i = tid; i < 4096; i += 128) {
        int l = i >> 6, s = i & 63;
        float v = __expf(2.f * S[l * 65 + s] - rm[l] - cm[s]) * rinv[l] * cinv[s];
        outc[i] = v;
        if (v > best) { best = v; bidx = i; }
    }
    redv[tid] = best; redi[tid] = bidx;
    __syncthreads();

    if (tid == 0) {
        float b = redv[0]; int bi = redi[0];
        for (int t = 1; t < 128; ++t) {
            float v = redv[t];
            if (v > b || (v == b && redi[t] < bi)) { b = v; bi = redi[t]; }
        }
        bool valid = b > 0.01f;
        out[MCONF_OFF + m] = valid ? b : 0.f;
        out[VALID_OFF + m] = valid ? 1.f : 0.f;
        int l = bi >> 6, s = bi & 63;
        int ii = i_ids_c[m], jj = j_ids_c[m];
        int x0 = (ii % 80) * 4 + (l & 7) - 4;
        int y0 = (ii / 80) * 4 + (l >> 3) - 4;
        int x1 = (jj % 80) * 4 + (s & 7) - 4;
        int y1 = (jj / 80) * 4 + (s >> 3) - 4;
        g_coords[m] = make_int4(x0, y0, x1, y1);
    }
}

// ---------------------------------------------------------------------------
// K2: gather 3x3 patches (zero pad) -> g_X[m][q*192 + icc]
// 2 matches per block, 192 threads (thread = (match_local, ic))
// ---------------------------------------------------------------------------
__global__ void k2_gather(const float* __restrict__ f0w, const float* __restrict__ f1w,
                          const int* __restrict__ b_ids) {
    const int t  = threadIdx.x;
    const int ml = t / 96, ic = t - ml * 96;
    const int m  = blockIdx.x * 2 + ml;
    const int4 cd = g_coords[m];
    const int b = b_ids[m];
    const float* b0 = f0w + ((size_t)b * 96 + ic) * 102400;
    const float* b1 = f1w + ((size_t)b * 96 + ic) * 102400;
    __nv_bfloat16* X = g_X + (size_t)m * 1728;
#pragma unroll
    for (int q = 0; q < 9; ++q) {
        int dy = q / 3, dx = q - dy * 3;
        int y = cd.y - 1 + dy, x = cd.x - 1 + dx;
        float v0 = ((unsigned)y < 320u && (unsigned)x < 320u) ? b0[y * 320 + x] : 0.f;
        X[q * 192 + ic] = __float2bfloat16(v0);
        y = cd.w - 1 + dy; x = cd.z - 1 + dx;
        float v1 = ((unsigned)y < 320u && (unsigned)x < 320u) ? b1[y * 320 + x] : 0.f;
        X[q * 192 + 96 + ic] = __float2bfloat16(v1);
    }
}

// ---------------------------------------------------------------------------
// K3: bf16 mma GEMM, block 128x64, Kstage=64, 3-stage cp.async, ldmatrix.
// 128 threads = 4 warps (2m x 2n), warp tile 64x32.
// which==0: g_X(8192x1728) @ g_A1[n][k]  -> lrelu -> g_R bf16
// which==1: g_R(8192x1728) @ g_W2b[n][k] -> lrelu -> g_out2 f32
// dynamic smem: 3*(128+64)*72*2 = 82944 B
// ---------------------------------------------------------------------------
__global__ void __launch_bounds__(128) k3_gemm(int which) {
    extern __shared__ __align__(16) __nv_bfloat16 sm3[];
    __nv_bfloat16* As = sm3;              // [3][128*72]
    __nv_bfloat16* Bs = sm3 + 3 * 9216;   // [3][64*72]

    const __nv_bfloat16* A  = which ? g_R   : g_X;
    const __nv_bfloat16* Bm = which ? g_W2b : g_A1;

    const int tid = threadIdx.x;
    const int rowbase = blockIdx.x * 128;
    const int colbase = blockIdx.y * 64;
    const int warp = tid >> 5, lane = tid & 31;
    const int wm = warp >> 1, wn = warp & 1;
    const int mi = lane >> 3, rr = lane & 7;
    const int gid = lane >> 2, tq = lane & 3;
    const int a_rsel = (mi & 1) * 8 + rr;
    const int a_csel = (mi >> 1) * 8;
    const int b_roff = (mi >> 1) * 8 + rr;
    const int b_csel = (mi & 1) * 8;

    float c[4][4][4];
#pragma unroll
    for (int i = 0; i < 4; ++i)
#pragma unroll
        for (int j = 0; j < 4; ++j)
#pragma unroll
            for (int r = 0; r < 4; ++r) c[i][j][r] = 0.f;

    auto copy = [&](int st, int kt) {
        int k0 = kt * 64;
#pragma unroll
        for (int u = 0; u < 8; ++u) {
            int ch = tid + u * 128;
            int r = ch >> 3, sg = ch & 7;
            cpasync16(&As[st * 9216 + r * 72 + sg * 8],
                      A + (size_t)(rowbase + r) * 1728 + k0 + sg * 8);
        }
#pragma unroll
        for (int u = 0; u < 4; ++u) {
            int ch = tid + u * 128;
            int r = ch >> 3, sg = ch & 7;
            cpasync16(&Bs[st * 4608 + r * 72 + sg * 8],
                      Bm + (size_t)(colbase + r) * 1728 + k0 + sg * 8);
        }
    };

    const int KT = 27;                 // 1728 / 64
    copy(0, 0);
    asm volatile("cp.async.commit_group;");
    copy(1, 1);
    asm volatile("cp.async.commit_group;");

    for (int kt = 0; kt < KT; ++kt) {
        int st = kt % 3;
        if (kt + 2 < KT) copy((kt + 2) % 3, kt + 2);
        asm volatile("cp.async.commit_group;");      // one group per iter (maybe empty)
        asm volatile("cp.async.wait_group 2;");
        __syncthreads();

        const __nv_bfloat16* Ab = As + st * 9216;
        const __nv_bfloat16* Bb = Bs + st * 4608;
#pragma unroll
        for (int kk = 0; kk < 64; kk += 16) {
            unsigned a[4][4];
#pragma unroll
            for (int mt = 0; mt < 4; ++mt)
                ldsm4(a[mt], Ab + (wm * 64 + mt * 16 + a_rsel) * 72 + kk + a_csel);
            unsigned b0[4], b1[4];
            ldsm4(b0, Bb + (wn * 32 + b_roff) * 72 + kk + b_csel);
            ldsm4(b1, Bb + (wn * 32 + 16 + b_roff) * 72 + kk + b_csel);
#pragma unroll
            for (int mt = 0; mt < 4; ++mt) {
                mma16816(c[mt][0], a[mt], b0[0], b0[1]);
                mma16816(c[mt][1], a[mt], b0[2], b0[3]);
                mma16816(c[mt][2], a[mt], b1[0], b1[1]);
                mma16816(c[mt][3], a[mt], b1[2], b1[3]);
            }
        }
        __syncthreads();
    }

#pragma unroll
    for (int mt = 0; mt < 4; ++mt)
#pragma unroll
        for (int nt = 0; nt < 4; ++nt) {
            int r0 = rowbase + wm * 64 + mt * 16 + gid;
            int c0 = colbase + wn * 32 + nt * 8 + tq * 2;
            float v00 = lrelu(c[mt][nt][0]), v01 = lrelu(c[mt][nt][1]);
            float v10 = lrelu(c[mt][nt][2]), v11 = lrelu(c[mt][nt][3]);
            if (!which) {
                *(__nv_bfloat162*)(g_R + (size_t)r0 * 1728 + c0) =
                    __floats2bfloat162_rn(v00, v01);
                *(__nv_bfloat162*)(g_R + (size_t)(r0 + 8) * 1728 + c0) =
                    __floats2bfloat162_rn(v10, v11);
            } else {
                *(float2*)(g_out2 + (size_t)r0 * 192 + c0) = make_float2(v00, v01);
                *(float2*)(g_out2 + (size_t)(r0 + 8) * 192 + c0) = make_float2(v10, v11);
            }
        }
}

// ---------------------------------------------------------------------------
// K4: conv3 (1x1, 4 outs) + tanh + mkpts. One warp per match.
// ---------------------------------------------------------------------------
__global__ void k4_fin(const float* __restrict__ w3, float* __restrict__ out) {
    const int m = blockIdx.x * 8 + (threadIdx.x >> 5);
    const int lane = threadIdx.x & 31;
    const float* r = g_out2 + (size_t)m * 192;
    float a0 = 0.f, a1 = 0.f, a2 = 0.f, a3 = 0.f;
#pragma unroll
    for (int i = lane; i < 192; i += 32) {
        float v = r[i];
        a0 += w3[i] * v;
        a1 += w3[192 + i] * v;
        a2 += w3[384 + i] * v;
        a3 += w3[576 + i] * v;
    }
#pragma unroll
    for (int o = 16; o; o >>= 1) {
        a0 += __shfl_xor_sync(0xffffffffu, a0, o);
        a1 += __shfl_xor_sync(0xffffffffu, a1, o);
        a2 += __shfl_xor_sync(0xffffffffu, a2, o);
        a3 += __shfl_xor_sync(0xffffffffu, a3, o);
    }
    if (lane == 0) {
        int4 cd = g_coords[m];
        out[MK0_OFF + 2 * m]     = ((float)cd.x + tanhf(a0) * 0.5f) * 2.f;
        out[MK0_OFF + 2 * m + 1] = ((float)cd.y + tanhf(a1) * 0.5f) * 2.f;
        out[MK1_OFF + 2 * m]     = ((float)cd.z + tanhf(a2) * 0.5f) * 2.f;
        out[MK1_OFF + 2 * m + 1] = ((float)cd.w + tanhf(a3) * 0.5f) * 2.f;
    }
}

// ---------------------------------------------------------------------------
extern "C" void kernel_launch(void* const* d_in, const int* in_sizes, int n_in,
                              void* d_out, int out_size) {
    const float* f0u  = (const float*)d_in[0];
    const float* f1u  = (const float*)d_in[1];
    const float* f0w  = (const float*)d_in[2];
    const float* f1w  = (const float*)d_in[3];
    const int*   bids = (const int*)d_in[4];
    const int*   iids = (const int*)d_in[5];
    const int*   jids = (const int*)d_in[6];
    const float* w1   = (const float*)d_in[7];
    const float* w2   = (const float*)d_in[8];
    const float* w3   = (const float*)d_in[9];
    float* out = (float*)d_out;

    cudaFuncSetAttribute(k1_sim, cudaFuncAttributeMaxDynamicSharedMemorySize, 71936);
    cudaFuncSetAttribute(k3_gemm, cudaFuncAttributeMaxDynamicSharedMemorySize, 82944);

    k0_w<<<(1728 * 1728 + 192 * 1728 + 255) / 256, 256>>>(w1, w2);
    k1_sim<<<M_MATCH, 128, 71936>>>(f0u, f1u, iids, jids, out);
    k2_gather<<<M_MATCH / 2, 192>>>(f0w, f1w, bids);
    k3_gemm<<<dim3(64, 27), 128, 82944>>>(0);   // conv1: N=1728
    k3_gemm<<<dim3(64, 3), 128, 82944>>>(1);    // conv2: N=192
    k4_fin<<<M_MATCH / 8, 256>>>(w3, out);
}